// round 1
// baseline (speedup 1.0000x reference)
#include <cuda_runtime.h>

#define NB 4
#define NK 128
#define NG 128

// ---- output layout (float32, tuple flattened & concatenated) ----
// rois    : [4,128,4]           offset 0        size 2048
// obj     : [4,128,1,1,1024]    offset 2048     size 524288
// deltas  : [4,128,4]           offset 526336   size 2048
// ranks   : [4,128]             offset 528384   size 512
// spatial : [4,128,32,32,1]     offset 528896   size 524288
#define OFF_ROIS    0
#define OFF_OBJ     2048
#define OFF_DELTAS  526336
#define OFF_RANKS   528384
#define OFF_SPATIAL 528896

// scratch (no allocations allowed)
__device__ int  g_order[NB * NK];   // order[b*K+o] = original proposal index p
__device__ int4 g_box[NB * NK];     // integer spatial box (by1,bx1,by2,bx2) per output slot

__global__ void setup_kernel(const float* __restrict__ proposals,
                             const float* __restrict__ gt_boxes,
                             const int*   __restrict__ gt_ranks,
                             float*       __restrict__ out)
{
    __shared__ float s_gt[NG * 4];
    __shared__ int   s_pos[NK];
    __shared__ int   s_dest[NK];

    const int b = blockIdx.x;
    const int p = threadIdx.x;           // one thread per proposal

    // load this image's GT boxes into shared
    const float* gtb = gt_boxes + b * NG * 4;
    for (int i = p; i < NG * 4; i += NK) s_gt[i] = gtb[i];
    __syncthreads();

    const float py1 = proposals[(b * NK + p) * 4 + 0];
    const float px1 = proposals[(b * NK + p) * 4 + 1];
    const float py2 = proposals[(b * NK + p) * 4 + 2];
    const float px2 = proposals[(b * NK + p) * 4 + 3];
    const float ap  = (py2 - py1) * (px2 - px1);

    float best = -1.0f;
    int   bidx = 0;
    #pragma unroll 4
    for (int j = 0; j < NG; j++) {
        const float gy1 = s_gt[j * 4 + 0];
        const float gx1 = s_gt[j * 4 + 1];
        const float gy2 = s_gt[j * 4 + 2];
        const float gx2 = s_gt[j * 4 + 3];
        const float iy1 = fmaxf(py1, gy1);
        const float ix1 = fmaxf(px1, gx1);
        const float iy2 = fminf(py2, gy2);
        const float ix2 = fminf(px2, gx2);
        const float inter = fmaxf(ix2 - ix1, 0.0f) * fmaxf(iy2 - iy1, 0.0f);
        const float ag = (gy2 - gy1) * (gx2 - gx1);
        const float iou = inter / (ap + ag - inter);
        if (iou > best) { best = iou; bidx = j; }   // first max wins (strict >)
    }
    const int pos = (best >= 0.5f) ? 1 : 0;
    s_pos[p] = pos;
    __syncthreads();

    // stable partition: positives first (original order), then negatives
    if (p == 0) {
        int np = 0;
        for (int i = 0; i < NK; i++) np += s_pos[i];
        int ip = 0, in_ = 0;
        for (int i = 0; i < NK; i++)
            s_dest[i] = s_pos[i] ? (ip++) : (np + (in_++));
    }
    __syncthreads();

    const int o = s_dest[p];
    g_order[b * NK + o] = p;

    float* out_rois   = out + OFF_ROIS;
    float* out_deltas = out + OFF_DELTAS;
    float* out_ranks  = out + OFF_RANKS;

    const int base = (b * NK + o) * 4;
    out_rois[base + 0] = py1;
    out_rois[base + 1] = px1;
    out_rois[base + 2] = py2;
    out_rois[base + 3] = px2;

    float gy1 = s_gt[bidx * 4 + 0];
    float gx1 = s_gt[bidx * 4 + 1];
    float gy2 = s_gt[bidx * 4 + 2];
    float gx2 = s_gt[bidx * 4 + 3];

    if (pos) {
        const float h  = py2 - py1, w  = px2 - px1;
        const float cy = py1 + 0.5f * h, cx = px1 + 0.5f * w;
        const float gh = gy2 - gy1, gw = gx2 - gx1;
        const float gcy = gy1 + 0.5f * gh, gcx = gx1 + 0.5f * gw;
        out_deltas[base + 0] = ((gcy - cy) / h) / 0.1f;
        out_deltas[base + 1] = ((gcx - cx) / w) / 0.1f;
        out_deltas[base + 2] = logf(gh / h) / 0.2f;
        out_deltas[base + 3] = logf(gw / w) / 0.2f;
        out_ranks[b * NK + o] = (float)gt_ranks[b * NG + bidx];
    } else {
        out_deltas[base + 0] = 0.0f;
        out_deltas[base + 1] = 0.0f;
        out_deltas[base + 2] = 0.0f;
        out_deltas[base + 3] = 0.0f;
        out_ranks[b * NK + o] = 0.0f;
        gy1 = gx1 = gy2 = gx2 = 0.0f;   // roi_gt = 0 for negatives
    }

    // spatial box: norm_boxes window transform + denorm + round-half-even
    const float win0 = 128.0f / 1023.0f;
    const float win2 = 895.0f / 1023.0f;
    const float wsc  = win2 - win0;     // f32 arithmetic matches jnp
    int by1 = (int)rintf(((gy1 - win0) / wsc) * 479.0f + 0.0f);
    int bx1 = (int)rintf((gx1 / 1.0f)        * 639.0f + 0.0f);
    int by2 = (int)rintf(((gy2 - win0) / wsc) * 479.0f + 1.0f);
    int bx2 = (int)rintf((gx2 / 1.0f)        * 639.0f + 1.0f);
    const int area = (by2 - by1) * (bx2 - bx1);
    if (!(area > 0)) { by1 = bx1 = by2 = bx2 = 0; }
    g_box[b * NK + o] = make_int4(by1, bx1, by2, bx2);
}

__global__ void scatter_kernel(const float* __restrict__ obj_feat,
                               float*       __restrict__ out)
{
    const int beta = blockIdx.x;        // b*K + o
    const int t    = threadIdx.x;       // 256 threads
    const int b    = beta >> 7;
    const int p    = g_order[beta];

    // obj permuted copy: 1024 floats = 256 float4
    const float4* src = (const float4*)(obj_feat + (size_t)(b * NK + p) * 1024);
    float4*       dst = (float4*)(out + OFF_OBJ + (size_t)beta * 1024);
    dst[t] = src[t];

    // spatial feature: 32x32, rows [4,28) carry the 24x32 resized mask,
    // each value = 0.25*(fy(20i+9)+fy(20i+10))*(fx(20j+9)+fx(20j+10))
    const int4 bx = g_box[beta];
    float* sp = out + OFF_SPATIAL + (size_t)beta * 1024;
    #pragma unroll
    for (int e = t; e < 1024; e += 256) {
        const int row = e >> 5;
        const int col = e & 31;
        float v = 0.0f;
        if (row >= 4 && row < 28) {
            const int i  = row - 4;
            const int r1 = 20 * i + 9;
            const int r2 = r1 + 1;
            const int c1 = 20 * col + 9;
            const int c2 = c1 + 1;
            const float fy = (float)((bx.x < r1) && (r1 < bx.z))
                           + (float)((bx.x < r2) && (r2 < bx.z));
            const float fx = (float)((bx.y < c1) && (c1 < bx.w))
                           + (float)((bx.y < c2) && (c2 < bx.w));
            v = 0.25f * fy * fx;
        }
        sp[e] = v;
    }
}

extern "C" void kernel_launch(void* const* d_in, const int* in_sizes, int n_in,
                              void* d_out, int out_size)
{
    const float* proposals = (const float*)d_in[0];
    const float* obj_feat  = (const float*)d_in[1];
    const float* gt_boxes  = (const float*)d_in[2];
    const int*   gt_ranks  = (const int*)  d_in[3];
    float* out = (float*)d_out;

    setup_kernel<<<NB, NK>>>(proposals, gt_boxes, gt_ranks, out);
    scatter_kernel<<<NB * NK, 256>>>(obj_feat, out);
}